// round 10
// baseline (speedup 1.0000x reference)
#include <cuda_runtime.h>
#include <math.h>

#define S_   16
#define B_   8
#define H_   16
#define DH_  64
#define D_   1024
#define LC_  8192
#define LT_  8208
#define CH_  128
#define NCH_ 65
#define KSTR_ 68
#define PSTR_ 132
#define ROWSTRIDE_ 8192
#define KOFF_ 131072
#define VOFF_ (131072 + 67239936)

__device__ float g_q[S_ * B_ * D_];
__device__ float g_ctx[S_ * B_ * D_];

// ---------------- cp.async helpers ----------------
__device__ __forceinline__ void cp_async16(unsigned saddr, const void* gptr) {
    asm volatile("cp.async.cg.shared.global [%0], [%1], 16;" :: "r"(saddr), "l"(gptr));
}
__device__ __forceinline__ void cp_commit() {
    asm volatile("cp.async.commit_group;" ::: "memory");
}
template <int N> __device__ __forceinline__ void cp_wait() {
    asm volatile("cp.async.wait_group %0;" :: "n"(N) : "memory");
}
__device__ __forceinline__ unsigned smem_u32(const void* p) {
    return (unsigned)__cvta_generic_to_shared(p);
}

// ---------------- tf32 mma helpers ----------------
__device__ __forceinline__ unsigned toTF32(float x) {
    unsigned r;
    asm("cvt.rna.tf32.f32 %0, %1;" : "=r"(r) : "f"(x));
    return r;
}
__device__ __forceinline__ void mma_tf32(float& c0, float& c1, float& c2, float& c3,
                                         unsigned a0, unsigned a1, unsigned a2, unsigned a3,
                                         unsigned b0, unsigned b1) {
    asm volatile(
        "mma.sync.aligned.m16n8k8.row.col.f32.tf32.tf32.f32 "
        "{%0,%1,%2,%3},{%4,%5,%6,%7},{%8,%9},{%0,%1,%2,%3};"
        : "+f"(c0), "+f"(c1), "+f"(c2), "+f"(c3)
        : "r"(a0), "r"(a1), "r"(a2), "r"(a3), "r"(b0), "r"(b1));
}

// ---------------- f32x2 packed FMA helpers ----------------
__device__ __forceinline__ unsigned long long pack2(float a) {
    unsigned long long p;
    asm("mov.b64 %0, {%1, %1};" : "=l"(p) : "f"(a));
    return p;
}
__device__ __forceinline__ void ffma2(unsigned long long& c,
                                      unsigned long long a, unsigned long long b) {
    asm("fma.rn.f32x2 %0, %1, %2, %0;" : "+l"(c) : "l"(a), "l"(b));
}
__device__ __forceinline__ float2 unpack2(unsigned long long c) {
    float x, y;
    asm("mov.b64 {%0, %1}, %2;" : "=f"(x), "=f"(y) : "l"(c));
    return make_float2(x, y);
}

// ============ shared pipelined 64x64 f32x2 GEMM body ============
// C(64x64) += A(64x1024 rows r0..r0+63) * B(1024x64 cols c0..c0+63)
// 4-stage cp.async ring for B, depth-2 register prefetch for A.
// Caller provides per-thread output handling via epilogue lambda.
template <typename EPI>
__device__ __forceinline__ void gemm64x64_f32x2(
    const float* __restrict__ A, const float* __restrict__ Bm,
    int r0, int c0, float (*As)[16][KSTR_], float (*Bs)[16][KSTR_],
    EPI&& epilogue)
{
    const int tid = threadIdx.x;
    const int ty = tid >> 4;
    const int tx = tid & 15;
    const int am = tid >> 2, ak = (tid & 3) << 2;
    const int bk = tid >> 4, bn = (tid & 15) << 2;

    unsigned long long c01[4] = {0ull, 0ull, 0ull, 0ull};
    unsigned long long c23[4] = {0ull, 0ull, 0ull, 0ull};

    auto issueB = [&](int kt) {
        cp_async16(smem_u32(&Bs[kt & 3][bk][bn]),
                   &Bm[(size_t)(kt * 16 + bk) * D_ + c0 + bn]);
    };
    auto ldgA = [&](int kt) {
        return *(const float4*)&A[(size_t)(r0 + am) * D_ + kt * 16 + ak];
    };
    auto storeA = [&](int buf, float4 v) {
        As[buf][ak + 0][am] = v.x; As[buf][ak + 1][am] = v.y;
        As[buf][ak + 2][am] = v.z; As[buf][ak + 3][am] = v.w;
    };

    issueB(0); cp_commit();
    issueB(1); cp_commit();
    issueB(2); cp_commit();
    storeA(0, ldgA(0));
    float4 rA[2];
    rA[0] = ldgA(1);
    rA[1] = ldgA(2);

    for (int kt = 0; kt < 64; ++kt) {
        cp_wait<2>();
        __syncthreads();
        if (kt + 3 < 64) issueB(kt + 3);
        cp_commit();

        const int ab = kt & 1, bb = kt & 3;
        #pragma unroll
        for (int k = 0; k < 16; ++k) {
            const float4 a4 = *(const float4*)&As[ab][k][ty << 2];
            const ulonglong2 bp = *(const ulonglong2*)&Bs[bb][k][tx << 2];
            const unsigned long long p0 = pack2(a4.x), p1 = pack2(a4.y);
            const unsigned long long p2 = pack2(a4.z), p3 = pack2(a4.w);
            ffma2(c01[0], p0, bp.x); ffma2(c23[0], p0, bp.y);
            ffma2(c01[1], p1, bp.x); ffma2(c23[1], p1, bp.y);
            ffma2(c01[2], p2, bp.x); ffma2(c23[2], p2, bp.y);
            ffma2(c01[3], p3, bp.x); ffma2(c23[3], p3, bp.y);
        }

        if (kt < 63) {
            storeA(kt & 1 ? 0 : 1, rA[kt & 1]);
            if (kt + 3 < 64) rA[kt & 1] = ldgA(kt + 3);
        }
    }

    #pragma unroll
    for (int r = 0; r < 4; ++r) {
        const float2 lo = unpack2(c01[r]);
        const float2 hi = unpack2(c23[r]);
        epilogue(r0 + (ty << 2) + r, c0 + (tx << 2),
                 make_float4(lo.x, lo.y, hi.x, hi.y));
    }
}

// ---------------- QKV projection ----------------
__global__ void __launch_bounds__(256)
qkv_kernel(const float* __restrict__ x,
           const float* __restrict__ Wq, const float* __restrict__ Wk,
           const float* __restrict__ Wv, float* __restrict__ out)
{
    const int mat = blockIdx.z;
    const float* __restrict__ W = (mat == 0) ? Wq : (mat == 1) ? Wk : Wv;
    __shared__ __align__(16) float As[2][16][KSTR_];
    __shared__ __align__(16) float Bs[4][16][KSTR_];

    gemm64x64_f32x2(x, W, blockIdx.y * 64, blockIdx.x * 64, As, Bs,
        [&](int row, int col, float4 res) {
            const int s = row >> 3, b = row & 7;
            if (mat == 0) {
                *(float4*)&g_q[(size_t)row * D_ + col] = res;
            } else {
                float* dst = out + ((mat == 1) ? KOFF_ : VOFF_);
                *(float4*)&dst[(size_t)(LC_ + s) * ROWSTRIDE_ + b * D_ + col] = res;
            }
        });
}

// ---------------- output projection: res = ctx @ Wo ----------------
__global__ void __launch_bounds__(256)
oproj_kernel(const float* __restrict__ Wo, float* __restrict__ out)
{
    __shared__ __align__(16) float As[2][16][KSTR_];
    __shared__ __align__(16) float Bs[4][16][KSTR_];

    gemm64x64_f32x2(g_ctx, Wo, blockIdx.y * 64, blockIdx.x * 64, As, Bs,
        [&](int row, int col, float4 res) {
            *(float4*)&out[(size_t)row * D_ + col] = res;
        });
}

// ---------------- fused attention + cache copy (tf32 mma) ----------------
__global__ void __launch_bounds__(256, 1)
attn_kernel(const float* __restrict__ cK, const float* __restrict__ cV,
            float* __restrict__ out)
{
    extern __shared__ __align__(16) float sh[];
    float* sQ  = sh;
    float* sK0 = sQ  + S_ * DH_;
    float* sV0 = sK0 + CH_ * KSTR_;
    float* sK1 = sV0 + CH_ * KSTR_;
    float* sV1 = sK1 + CH_ * KSTR_;
    float* sP  = sV1 + CH_ * KSTR_;
    float* sM  = sP  + S_ * PSTR_;
    float* sL  = sM + 16;
    float* sF  = sL + 16;

    const int tid  = threadIdx.x;
    const int lane = tid & 31;
    const int w    = tid >> 5;
    const int bh   = blockIdx.x;
    const int b    = bh >> 4, h = bh & 15;
    const int ts   = tid >> 4;
    const int tt   = tid & 15;
    const int g    = lane >> 2;
    const int t4   = lane & 3;

    {   // load Q, pre-scaled by 1/sqrt(DH)
        const float4 q4 = *(const float4*)&g_q[(size_t)(ts * B_ + b) * D_ + h * DH_ + (tt << 2)];
        float* dst = &sQ[ts * DH_ + (tt << 2)];
        dst[0] = q4.x * 0.125f; dst[1] = q4.y * 0.125f;
        dst[2] = q4.z * 0.125f; dst[3] = q4.w * 0.125f;
    }
    if (tid < 16) { sM[tid] = -1e30f; sL[tid] = 0.f; }

    float* outK = out + KOFF_;
    float* outV = out + VOFF_;
    const size_t baseBH = (size_t)bh * DH_;

    auto issue = [&](int c, float* dK, float* dV) {
        const int t0 = c * CH_;
        const int n = (t0 + CH_ <= LT_ ? CH_ : LT_ - t0) * 16;
        for (int idx = tid; idx < n; idx += 256) {
            const int r = idx >> 4, f = (idx & 15) << 2;
            const int t = t0 + r;
            const size_t gg = (size_t)t * ROWSTRIDE_ + baseBH + f;
            const float* srcK = (t < LC_) ? (cK + gg) : (outK + gg);
            const float* srcV = (t < LC_) ? (cV + gg) : (outV + gg);
            cp_async16(smem_u32(&dK[r * KSTR_ + f]), srcK);
            cp_async16(smem_u32(&dV[r * KSTR_ + f]), srcV);
        }
        cp_commit();
    };

    issue(0, sK0, sV0);
    __syncthreads();

    unsigned qA[8][4];
    #pragma unroll
    for (int ks = 0; ks < 8; ++ks) {
        qA[ks][0] = toTF32(sQ[g * DH_       + ks * 8 + t4]);
        qA[ks][1] = toTF32(sQ[(g + 8) * DH_ + ks * 8 + t4]);
        qA[ks][2] = toTF32(sQ[g * DH_       + ks * 8 + t4 + 4]);
        qA[ks][3] = toTF32(sQ[(g + 8) * DH_ + ks * 8 + t4 + 4]);
    }

    float oc[2][4] = {{0.f,0.f,0.f,0.f},{0.f,0.f,0.f,0.f}};

    for (int c = 0; c < NCH_; ++c) {
        float* bK = (c & 1) ? sK1 : sK0;
        float* bV = (c & 1) ? sV1 : sV0;
        if (c + 1 < NCH_) {
            issue(c + 1, (c & 1) ? sK0 : sK1, (c & 1) ? sV0 : sV1);
            cp_wait<1>();
        } else {
            cp_wait<0>();
        }
        __syncthreads();

        const int t0   = c * CH_;
        const int rows = (t0 + CH_ <= LT_) ? CH_ : (LT_ - t0);

        // scores via mma: warp w computes cols [16w, 16w+16)
        #pragma unroll
        for (int nt = 0; nt < 2; ++nt) {
            const int n0 = (w << 4) + (nt << 3);
            float c0 = 0.f, c1 = 0.f, c2 = 0.f, c3 = 0.f;
            #pragma unroll
            for (int ks = 0; ks < 8; ++ks) {
                const unsigned b0 = toTF32(bK[(n0 + g) * KSTR_ + ks * 8 + t4]);
                const unsigned b1 = toTF32(bK[(n0 + g) * KSTR_ + ks * 8 + t4 + 4]);
                mma_tf32(c0, c1, c2, c3,
                         qA[ks][0], qA[ks][1], qA[ks][2], qA[ks][3], b0, b1);
            }
            *(float2*)&sP[g * PSTR_       + n0 + (t4 << 1)] = make_float2(c0, c1);
            *(float2*)&sP[(g + 8) * PSTR_ + n0 + (t4 << 1)] = make_float2(c2, c3);
        }
        __syncthreads();

        // online softmax; store P pre-rounded to tf32 (masked -> 0)
        {
            float lm = -1e30f;
            #pragma unroll
            for (int j = 0; j < 8; ++j) {
                const int t = tt + (j << 4);
                const bool valid = (t < rows) && (t0 + t - LC_ <= ts);
                if (valid) lm = fmaxf(lm, sP[ts * PSTR_ + t]);
            }
            #pragma unroll
            for (int o = 8; o >= 1; o >>= 1)
                lm = fmaxf(lm, __shfl_xor_sync(0xffffffffu, lm, o));
            const float mold = sM[ts];
            const float mnew = fmaxf(mold, lm);
            float ls = 0.f;
            #pragma unroll
            for (int j = 0; j < 8; ++j) {
                const int t = tt + (j << 4);
                const bool valid = (t < rows) && (t0 + t - LC_ <= ts);
                float p = 0.f;
                if (valid) p = __expf(sP[ts * PSTR_ + t] - mnew);
                sP[ts * PSTR_ + t] = __uint_as_float(toTF32(p));
                ls += p;
            }
            #pragma unroll
            for (int o = 8; o >= 1; o >>= 1)
                ls += __shfl_xor_sync(0xffffffffu, ls, o);
            if (tt == 0) {
                const float fac = __expf(mold - mnew);
                sL[ts] = sL[ts] * fac + ls;
                sM[ts] = mnew;
                sF[ts] = fac;
            }
        }
        __syncthreads();

        // phase 3 (warp-specialized): warps 0-3 PV, warps 4-7 cache copy
        if (w < 4) {
            const float f0 = sF[g], f1 = sF[g + 8];
            #pragma unroll
            for (int nt = 0; nt < 2; ++nt) {
                oc[nt][0] *= f0; oc[nt][1] *= f0;
                oc[nt][2] *= f1; oc[nt][3] *= f1;
            }
            #pragma unroll
            for (int ks = 0; ks < 16; ++ks) {
                const unsigned a0 = __float_as_uint(sP[g * PSTR_       + ks * 8 + t4]);
                const unsigned a1 = __float_as_uint(sP[(g + 8) * PSTR_ + ks * 8 + t4]);
                const unsigned a2 = __float_as_uint(sP[g * PSTR_       + ks * 8 + t4 + 4]);
                const unsigned a3 = __float_as_uint(sP[(g + 8) * PSTR_ + ks * 8 + t4 + 4]);
                #pragma unroll
                for (int nt = 0; nt < 2; ++nt) {
                    const int n0 = (w << 4) + (nt << 3);
                    const unsigned b0 = toTF32(bV[(ks * 8 + t4) * KSTR_     + n0 + g]);
                    const unsigned b1 = toTF32(bV[(ks * 8 + t4 + 4) * KSTR_ + n0 + g]);
                    mma_tf32(oc[nt][0], oc[nt][1], oc[nt][2], oc[nt][3],
                             a0, a1, a2, a3, b0, b1);
                }
            }
        } else if (t0 < LC_) {
            for (int idx = tid - 128; idx < CH_ * 16; idx += 128) {
                const int r = idx >> 4, f = (idx & 15) << 2;
                const size_t gg = (size_t)(t0 + r) * ROWSTRIDE_ + baseBH + f;
                *(float4*)&outK[gg] = *(const float4*)&bK[r * KSTR_ + f];
                *(float4*)&outV[gg] = *(const float4*)&bV[r * KSTR_ + f];
            }
        }
        __syncthreads();
    }

    if (w < 4) {
        const float inv0 = 1.f / sL[g];
        const float inv1 = 1.f / sL[g + 8];
        #pragma unroll
        for (int nt = 0; nt < 2; ++nt) {
            const int n0 = (w << 4) + (nt << 3);
            const int col = h * DH_ + n0 + (t4 << 1);
            *(float2*)&g_ctx[(size_t)(g * B_ + b) * D_ + col] =
                make_float2(oc[nt][0] * inv0, oc[nt][1] * inv0);
            *(float2*)&g_ctx[(size_t)((g + 8) * B_ + b) * D_ + col] =
                make_float2(oc[nt][2] * inv1, oc[nt][3] * inv1);
        }
    }
}

#define SMEM_ATTN_BYTES ((S_*DH_ + 4*CH_*KSTR_ + S_*PSTR_ + 48) * 4)

extern "C" void kernel_launch(void* const* d_in, const int* in_sizes, int n_in,
                              void* d_out, int out_size)
{
    const float* x  = (const float*)d_in[0];
    const float* ck = (const float*)d_in[1];
    const float* cv = (const float*)d_in[2];
    const float* Wq = (const float*)d_in[3];
    const float* Wk = (const float*)d_in[4];
    const float* Wv = (const float*)d_in[5];
    const float* Wo = (const float*)d_in[6];
    float* out = (float*)d_out;

    cudaFuncSetAttribute(attn_kernel,
        cudaFuncAttributeMaxDynamicSharedMemorySize, SMEM_ATTN_BYTES);

    qkv_kernel<<<dim3(16, 2, 3), 256>>>(x, Wq, Wk, Wv, out);
    attn_kernel<<<B_ * H_, 256, SMEM_ATTN_BYTES>>>(ck, cv, out);
    oproj_kernel<<<dim3(16, 2), 256>>>(Wo, out);
}